// round 16
// baseline (speedup 1.0000x reference)
#include <cuda_runtime.h>
#include <cuda_bf16.h>
#include <cstdint>
#include <math.h>

// NT-Xent loss, N=4096, D=256.
// loss = mean_i( log(sum_{j!=i} e^{2 zn_i.zn_j}) - 2 zn_i.zn_{i^4096} )
// R16: clean A-stationary fp8 symmetric GEMM (R15 redo without redundant MMAs):
//      warp tile 16x64, resident A frags, 4-group B ldsm per k-step, direct
//      row atomics, tile-gated masks, 2 CTAs/SM persistent grid.

#define NROWS 8192
#define NHALF 4096
#define DDIM  256
#define BM 128
#define BN 64
#define NTILE 64
#define NCTA 296
#define NTHREADS 256
#define A_BYTES (BM * DDIM)        // 32768
#define B_BYTES (BN * DDIM)        // 16384
#define RED_BYTES (8 * 64 * 4)     // red_col[8][64]
#define DYN_BYTES (A_BYTES + 2 * B_BYTES + RED_BYTES + 1024)

__device__ __align__(16) uint8_t g_zb[NROWS * DDIM];   // e4m3
__device__ float g_rowsum[NROWS];
__device__ float g_pair[NROWS];
__device__ unsigned g_cnt1;
__device__ unsigned g_cnt2;

// ---------------------------------------------------------------- helpers
__device__ __forceinline__ uint32_t smem_u32(const void* p) {
    uint32_t a;
    asm("{ .reg .u64 t; cvta.to.shared.u64 t, %1; cvt.u32.u64 %0, t; }" : "=r"(a) : "l"(p));
    return a;
}
__device__ __forceinline__ void ldsm_x4(uint32_t addr, uint32_t* r) {
    asm volatile("ldmatrix.sync.aligned.m8n8.x4.shared.b16 {%0,%1,%2,%3}, [%4];"
        : "=r"(r[0]), "=r"(r[1]), "=r"(r[2]), "=r"(r[3]) : "r"(addr));
}
__device__ __forceinline__ void mma_fp8(float* c, const uint32_t* a, const uint32_t* b) {
    asm volatile("mma.sync.aligned.m16n8k32.row.col.f32.e4m3.e4m3.f32 "
        "{%0,%1,%2,%3}, {%4,%5,%6,%7}, {%8,%9}, {%0,%1,%2,%3};"
        : "+f"(c[0]), "+f"(c[1]), "+f"(c[2]), "+f"(c[3])
        : "r"(a[0]), "r"(a[1]), "r"(a[2]), "r"(a[3]), "r"(b[0]), "r"(b[1]));
}
__device__ __forceinline__ void cp_async16(uint32_t dst, const void* src) {
    asm volatile("cp.async.cg.shared.global [%0], [%1], 16;" :: "r"(dst), "l"(src));
}
#define CP_COMMIT() asm volatile("cp.async.commit_group;" ::: "memory")
#define CP_WAIT0()  asm volatile("cp.async.wait_group 0;" ::: "memory")

__device__ __forceinline__ uint16_t f2e4m3x2(float hi, float lo) {
    uint16_t r;
    asm("cvt.rn.satfinite.e4m3x2.f32 %0, %1, %2;" : "=h"(r) : "f"(hi), "f"(lo));
    return r;
}
// fp8 tile rows: 256B, 16 chunks of 16B, swizzle c^(r&7)
__device__ __forceinline__ uint32_t tile_addr(uint32_t base, int row, int chunk) {
    return base + (uint32_t)row * 256u + (uint32_t)((chunk ^ (row & 7)) << 4);
}
__device__ __forceinline__ int rowof(int p) {
    return (p & 1) ? (NTILE - 1 - (p >> 1)) : (p >> 1);
}
__device__ __forceinline__ void load_A(uint32_t ubase, int row0, int tid) {
    #pragma unroll
    for (int it = 0; it < 8; it++) {
        int idx = tid + it * NTHREADS;
        int r = idx >> 4, c = idx & 15;
        cp_async16(tile_addr(ubase, r, c), g_zb + (size_t)(row0 + r) * DDIM + c * 16);
    }
}
__device__ __forceinline__ void load_B(uint32_t ubase, int row0, int tid) {
    #pragma unroll
    for (int it = 0; it < 4; it++) {
        int idx = tid + it * NTHREADS;
        int r = idx >> 4, c = idx & 15;
        cp_async16(tile_addr(ubase, r, c), g_zb + (size_t)(row0 + r) * DDIM + c * 16);
    }
}

// ---------------------------------------------------------- fused persistent kernel
__global__ __launch_bounds__(NTHREADS, 2) void k_fused(const float* __restrict__ z1,
                                                       const float* __restrict__ z2,
                                                       float* __restrict__ out) {
    extern __shared__ __align__(16) char dyn[];
    const int tid = threadIdx.x;
    const int wid = tid >> 5;          // 8 warps; warp owns rows [16w, 16w+16)
    const int lane = tid & 31;
    const int cta = blockIdx.x;

    // ---------------- phase 1: normalize -> e4m3 (warp per row) -------------------
    #pragma unroll
    for (int it = 0; it < 4; it++) {
        const int grp = cta + it * NCTA;
        if (grp < NROWS / 8) {
            const int row = grp * 8 + wid;
            const float* src = (row < NHALF) ? (z1 + (size_t)row * DDIM)
                                             : (z2 + (size_t)(row - NHALF) * DDIM);
            float4 v0 = ((const float4*)src)[lane * 2];
            float4 v1 = ((const float4*)src)[lane * 2 + 1];
            float ss = v0.x * v0.x + v0.y * v0.y + v0.z * v0.z + v0.w * v0.w
                     + v1.x * v1.x + v1.y * v1.y + v1.z * v1.z + v1.w * v1.w;
            #pragma unroll
            for (int o = 16; o; o >>= 1) ss += __shfl_xor_sync(0xFFFFFFFFu, ss, o);
            const float rn = 1.0f / fmaxf(sqrtf(ss), 1e-8f);
            uint16_t p0 = f2e4m3x2(v0.y * rn, v0.x * rn);
            uint16_t p1 = f2e4m3x2(v0.w * rn, v0.z * rn);
            uint16_t p2 = f2e4m3x2(v1.y * rn, v1.x * rn);
            uint16_t p3 = f2e4m3x2(v1.w * rn, v1.z * rn);
            uint2 packed;
            packed.x = (uint32_t)p0 | ((uint32_t)p1 << 16);
            packed.y = (uint32_t)p2 | ((uint32_t)p3 << 16);
            ((uint2*)(g_zb + (size_t)row * DDIM))[lane] = packed;
            if (lane == 0) g_rowsum[row] = 0.0f;
        }
    }

    // ---------------- grid barrier 1 ----------------------------------------------
    if (tid == 0) {
        __threadfence();
        atomicAdd(&g_cnt1, 1u);
        while (*(volatile unsigned*)&g_cnt1 < NCTA) { }
        __threadfence();
    }
    __syncthreads();

    // ---------------- phase 2: symmetric FP8 GEMM (128x64 tiles) -------------------
    uint32_t d32 = smem_u32(dyn);
    char* base = dyn + ((1024u - (d32 & 1023u)) & 1023u);
    const uint32_t uA  = smem_u32(base);
    const uint32_t uB0 = uA + A_BYTES;
    const uint32_t uB1 = uB0 + B_BYTES;
    float* red_col = (float*)(base + A_BYTES + 2 * B_BYTES);   // [8][64]

    // hoisted ldsm addresses: addr = P + ((ks<<5) ^ S)
    const int hl = lane >> 4;
    uint32_t PA, SA;
    {
        int r = wid * 16 + (lane & 15);
        PA = uA + (uint32_t)r * 256u + (uint32_t)((hl ^ (r & 1)) << 4);
        SA = (uint32_t)((r & 6) << 4);
    }
    uint32_t PBo[4], SB[4];            // 4 groups cover B rows (cols) 0..63
    #pragma unroll
    for (int ng = 0; ng < 4; ng++) {
        int rn = ng * 16 + (lane & 15);
        PBo[ng] = (uint32_t)rn * 256u + (uint32_t)((hl ^ (rn & 1)) << 4);
        SB[ng] = (uint32_t)((rn & 6) << 4);
    }

    // balanced chunk over 4160 tiles: 16 CTAs get 15, rest 14 (296*14+16 = 4160)
    const int count = 14 + (cta < 16 ? 1 : 0);
    int rem = cta * 14 + (cta < 16 ? cta : 16);
    int p = 0;
    for (;;) {
        int L = 2 * (NTILE - rowof(p));
        if (rem < L) break;
        rem -= L;
        p++;
    }
    int off = rem;

    int ti = rowof(p);
    load_A(uA, ti * BM, tid);
    load_B(uB0, (2 * ti + off) * BN, tid);
    CP_COMMIT();
    int cur_ti = ti;

    uint32_t aA[8][4];                 // resident A fragments (one x4 per k-step)
    bool haveA = false;

    for (int k = 0; k < count; k++) {
        ti = rowof(p);
        const int cj = 2 * ti + off;
        if (ti != cur_ti) {
            load_A(uA, ti * BM, tid);
            CP_COMMIT();
            cur_ti = ti;
            haveA = false;
        }
        CP_WAIT0();
        __syncthreads();

        if (k + 1 < count) {
            int p2 = p, o2 = off + 1;
            if (o2 >= 2 * (NTILE - rowof(p2))) { o2 = 0; p2++; }
            load_B((k & 1) ? uB0 : uB1, (2 * rowof(p2) + o2) * BN, tid);
            CP_COMMIT();
        }

        if (!haveA) {
            #pragma unroll
            for (int ks = 0; ks < 8; ks++)
                ldsm_x4(PA + (((uint32_t)ks << 5) ^ SA), aA[ks]);
            haveA = true;
        }

        const uint32_t uBc = (k & 1) ? uB1 : uB0;
        const int i0 = ti * BM, j0 = cj * BN;
        const bool colsum = (off >= 2);
        const bool maskt = (off < 2);
        const bool pairt = (ti < 32) && (off >= 64) && (off <= 65);

        float acc[8][4];               // nf covers cols nf*8 .. nf*8+7
        #pragma unroll
        for (int nf = 0; nf < 8; nf++)
            #pragma unroll
            for (int c = 0; c < 4; c++) acc[nf][c] = 0.0f;

        // ---- k-loop: A resident; 4 B ldsm groups + 8 mma per k-step ----
        #pragma unroll
        for (int ks = 0; ks < 8; ks++) {
            const uint32_t kbit = (uint32_t)(ks << 5);
            uint32_t bfr[8][2];
            #pragma unroll
            for (int ng = 0; ng < 4; ng++) {
                uint32_t q[4];
                ldsm_x4(uBc + PBo[ng] + (kbit ^ SB[ng]), q);
                bfr[ng * 2 + 0][0] = q[0]; bfr[ng * 2 + 0][1] = q[2];
                bfr[ng * 2 + 1][0] = q[1]; bfr[ng * 2 + 1][1] = q[3];
            }
            #pragma unroll
            for (int nf = 0; nf < 8; nf++)
                mma_fp8(acc[nf], aA[ks], bfr[nf]);
        }

        // ---- epilogue: pair capture, exp, tile-gated mask, row+col sums ----
        const int rbase = i0 + wid * 16 + (lane >> 2);
        const int cbase = j0 + (lane & 3) * 2;
        float slo = 0.0f, shi = 0.0f;

        #pragma unroll
        for (int h = 0; h < 2; h++) {
            float cs[8];
            #pragma unroll
            for (int x = 0; x < 8; x++) cs[x] = 0.0f;
            #pragma unroll
            for (int q = 0; q < 4; q++) {
                const int nf = h * 4 + q;
                const int col = cbase + nf * 8;
                if (pairt) {
                    if ((rbase ^ NHALF) == col) {
                        float v = 2.0f * acc[nf][0];
                        g_pair[rbase] = v; g_pair[col] = v;
                    }
                    if ((rbase ^ NHALF) == col + 1) {
                        float v = 2.0f * acc[nf][1];
                        g_pair[rbase] = v; g_pair[col + 1] = v;
                    }
                    if (((rbase + 8) ^ NHALF) == col) {
                        float v = 2.0f * acc[nf][2];
                        g_pair[rbase + 8] = v; g_pair[col] = v;
                    }
                    if (((rbase + 8) ^ NHALF) == col + 1) {
                        float v = 2.0f * acc[nf][3];
                        g_pair[rbase + 8] = v; g_pair[col + 1] = v;
                    }
                }
                float e0 = __expf(2.0f * acc[nf][0]);
                float e1 = __expf(2.0f * acc[nf][1]);
                float e2 = __expf(2.0f * acc[nf][2]);
                float e3 = __expf(2.0f * acc[nf][3]);
                if (maskt) {
                    e0 = (rbase == col)         ? 0.0f : e0;
                    e1 = (rbase == col + 1)     ? 0.0f : e1;
                    e2 = (rbase + 8 == col)     ? 0.0f : e2;
                    e3 = (rbase + 8 == col + 1) ? 0.0f : e3;
                }
                slo += e0 + e1;
                shi += e2 + e3;
                cs[q * 2]     += e0 + e2;
                cs[q * 2 + 1] += e1 + e3;
            }
            if (colsum) {
                #pragma unroll
                for (int x = 0; x < 8; x++) {
                    cs[x] += __shfl_xor_sync(0xFFFFFFFFu, cs[x], 4);
                    cs[x] += __shfl_xor_sync(0xFFFFFFFFu, cs[x], 8);
                    cs[x] += __shfl_xor_sync(0xFFFFFFFFu, cs[x], 16);
                }
                if (lane < 4) {
                    #pragma unroll
                    for (int q = 0; q < 4; q++) {
                        const int c = h * 32 + q * 8 + lane * 2;
                        red_col[wid * 64 + c]     = cs[q * 2];
                        red_col[wid * 64 + c + 1] = cs[q * 2 + 1];
                    }
                }
            }
        }
        // row sums: quad-reduce then direct atomics (warp owns the whole row)
        slo += __shfl_xor_sync(0xFFFFFFFFu, slo, 1);
        slo += __shfl_xor_sync(0xFFFFFFFFu, slo, 2);
        shi += __shfl_xor_sync(0xFFFFFFFFu, shi, 1);
        shi += __shfl_xor_sync(0xFFFFFFFFu, shi, 2);
        if ((lane & 3) == 0) {
            atomicAdd(&g_rowsum[rbase], slo);
            atomicAdd(&g_rowsum[rbase + 8], shi);
        }
        __syncthreads();
        if (colsum && tid < BN) {
            float s = 0.0f;
            #pragma unroll
            for (int w = 0; w < 8; w++) s += red_col[w * 64 + tid];
            atomicAdd(&g_rowsum[j0 + tid], s);
        }

        off++;
        if (off >= 2 * (NTILE - ti)) { off = 0; p++; }
    }

    // ---------------- grid barrier 2 + CTA0 finish ---------------------------------
    if (tid == 0) {
        __threadfence();
        atomicAdd(&g_cnt2, 1u);
    }
    if (cta == 0) {
        if (tid == 0) {
            while (*(volatile unsigned*)&g_cnt2 < NCTA) { }
            __threadfence();
        }
        __syncthreads();
        __shared__ float sh[NTHREADS];
        float s = 0.0f;
        #pragma unroll
        for (int u = 0; u < NROWS / NTHREADS; u++) {
            const int r = tid + u * NTHREADS;
            s += logf(g_rowsum[r]) - g_pair[r];
        }
        sh[tid] = s;
        __syncthreads();
        for (int o2 = NTHREADS / 2; o2; o2 >>= 1) {
            if (tid < o2) sh[tid] += sh[tid + o2];
            __syncthreads();
        }
        if (tid == 0) {
            out[0] = sh[0] * (1.0f / (float)NROWS);
            g_cnt1 = 0;
            g_cnt2 = 0;
        }
    }
}

// ---------------------------------------------------------------- launch
extern "C" void kernel_launch(void* const* d_in, const int* in_sizes, int n_in,
                              void* d_out, int out_size) {
    const float* z1 = (const float*)d_in[0];
    const float* z2 = (const float*)d_in[1];
    float* out = (float*)d_out;

    static int smem_set = 0;
    if (!smem_set) {
        cudaFuncSetAttribute(k_fused, cudaFuncAttributeMaxDynamicSharedMemorySize,
                             DYN_BYTES);
        smem_set = 1;
    }

    k_fused<<<NCTA, NTHREADS, DYN_BYTES>>>(z1, z2, out);
}

// round 17
// speedup vs baseline: 1.0050x; 1.0050x over previous
#include <cuda_runtime.h>
#include <cuda_bf16.h>
#include <cstdint>
#include <math.h>

// NT-Xent loss, N=4096, D=256.
// loss = mean_i( log(sum_{j!=i} e^{2 zn_i.zn_j}) - 2 zn_i.zn_{i^4096} )
// R17: R14 base (fp8 128x64 symmetric GEMM, 2 CTAs/SM persistent) with the
//      epilogue exp moved off MUFU onto the FMA pipe (magic-round + poly exp2).
//      Theory: kernel has been MUFU-bound since R6 (34M EX2 ~= 58us/SM-pipe).

#define NROWS 8192
#define NHALF 4096
#define DDIM  256
#define BM 128
#define BN 64
#define NTILE 64
#define NCTA 296
#define NTHREADS 256
#define A_BYTES (BM * DDIM)        // 32768
#define B_BYTES (BN * DDIM)        // 16384
#define RED_BYTES 2048             // red_row[2][128] + red_col[4][64]
#define DYN_BYTES (A_BYTES + 2 * B_BYTES + RED_BYTES + 1024)

__device__ __align__(16) uint8_t g_zb[NROWS * DDIM];   // e4m3
__device__ float g_rowsum[NROWS];
__device__ float g_pair[NROWS];
__device__ unsigned g_cnt1;
__device__ unsigned g_cnt2;

// ---------------------------------------------------------------- helpers
__device__ __forceinline__ uint32_t smem_u32(const void* p) {
    uint32_t a;
    asm("{ .reg .u64 t; cvta.to.shared.u64 t, %1; cvt.u32.u64 %0, t; }" : "=r"(a) : "l"(p));
    return a;
}
__device__ __forceinline__ void ldsm_x4(uint32_t addr, uint32_t* r) {
    asm volatile("ldmatrix.sync.aligned.m8n8.x4.shared.b16 {%0,%1,%2,%3}, [%4];"
        : "=r"(r[0]), "=r"(r[1]), "=r"(r[2]), "=r"(r[3]) : "r"(addr));
}
__device__ __forceinline__ void mma_fp8(float* c, const uint32_t* a, const uint32_t* b) {
    asm volatile("mma.sync.aligned.m16n8k32.row.col.f32.e4m3.e4m3.f32 "
        "{%0,%1,%2,%3}, {%4,%5,%6,%7}, {%8,%9}, {%0,%1,%2,%3};"
        : "+f"(c[0]), "+f"(c[1]), "+f"(c[2]), "+f"(c[3])
        : "r"(a[0]), "r"(a[1]), "r"(a[2]), "r"(a[3]), "r"(b[0]), "r"(b[1]));
}
__device__ __forceinline__ void cp_async16(uint32_t dst, const void* src) {
    asm volatile("cp.async.cg.shared.global [%0], [%1], 16;" :: "r"(dst), "l"(src));
}
#define CP_COMMIT() asm volatile("cp.async.commit_group;" ::: "memory")
#define CP_WAIT0()  asm volatile("cp.async.wait_group 0;" ::: "memory")

__device__ __forceinline__ uint16_t f2e4m3x2(float hi, float lo) {
    uint16_t r;
    asm("cvt.rn.satfinite.e4m3x2.f32 %0, %1, %2;" : "=h"(r) : "f"(hi), "f"(lo));
    return r;
}

// e^{2a} = 2^{a*2.8853900818} entirely on fma/alu pipes (no MUFU).
// |t| <= ~3.2; magic-number round-to-nearest, degree-4 Taylor of 2^f, |f|<=0.5.
__device__ __forceinline__ float fexp2a(float a) {
    const float t = a * 2.8853900818f;
    const float z = t + 12582912.0f;            // 1.5*2^23: RN integer in mantissa
    const float i = z - 12582912.0f;
    const float f = t - i;
    float p = 0.009618130f;
    p = fmaf(p, f, 0.055504110f);
    p = fmaf(p, f, 0.240226507f);
    p = fmaf(p, f, 0.693147181f);
    p = fmaf(p, f, 1.0f);
    return __int_as_float(__float_as_int(p) + (__float_as_int(z) << 23));
}

// fp8 tile rows: 256B, 16 chunks of 16B, swizzle c^(r&7)
__device__ __forceinline__ uint32_t tile_addr(uint32_t base, int row, int chunk) {
    return base + (uint32_t)row * 256u + (uint32_t)((chunk ^ (row & 7)) << 4);
}
__device__ __forceinline__ int rowof(int p) {
    return (p & 1) ? (NTILE - 1 - (p >> 1)) : (p >> 1);
}
__device__ __forceinline__ void load_A(uint32_t ubase, int row0, int tid) {
    #pragma unroll
    for (int it = 0; it < 8; it++) {
        int idx = tid + it * NTHREADS;
        int r = idx >> 4, c = idx & 15;
        cp_async16(tile_addr(ubase, r, c), g_zb + (size_t)(row0 + r) * DDIM + c * 16);
    }
}
__device__ __forceinline__ void load_B(uint32_t ubase, int row0, int tid) {
    #pragma unroll
    for (int it = 0; it < 4; it++) {
        int idx = tid + it * NTHREADS;
        int r = idx >> 4, c = idx & 15;
        cp_async16(tile_addr(ubase, r, c), g_zb + (size_t)(row0 + r) * DDIM + c * 16);
    }
}

// ---------------------------------------------------------- fused persistent kernel
__global__ __launch_bounds__(NTHREADS, 2) void k_fused(const float* __restrict__ z1,
                                                       const float* __restrict__ z2,
                                                       float* __restrict__ out) {
    extern __shared__ __align__(16) char dyn[];
    const int tid = threadIdx.x;
    const int wid = tid >> 5;
    const int lane = tid & 31;
    const int wm = wid & 3;            // 4 row groups of 32
    const int wn = wid >> 2;           // 2 col groups of 32
    const int cta = blockIdx.x;

    // ---------------- phase 1: normalize -> e4m3 (warp per row) -------------------
    #pragma unroll
    for (int it = 0; it < 4; it++) {
        const int grp = cta + it * NCTA;
        if (grp < NROWS / 8) {
            const int row = grp * 8 + wid;
            const float* src = (row < NHALF) ? (z1 + (size_t)row * DDIM)
                                             : (z2 + (size_t)(row - NHALF) * DDIM);
            float4 v0 = ((const float4*)src)[lane * 2];
            float4 v1 = ((const float4*)src)[lane * 2 + 1];
            float ss = v0.x * v0.x + v0.y * v0.y + v0.z * v0.z + v0.w * v0.w
                     + v1.x * v1.x + v1.y * v1.y + v1.z * v1.z + v1.w * v1.w;
            #pragma unroll
            for (int o = 16; o; o >>= 1) ss += __shfl_xor_sync(0xFFFFFFFFu, ss, o);
            const float rn = 1.0f / fmaxf(sqrtf(ss), 1e-8f);
            uint16_t p0 = f2e4m3x2(v0.y * rn, v0.x * rn);
            uint16_t p1 = f2e4m3x2(v0.w * rn, v0.z * rn);
            uint16_t p2 = f2e4m3x2(v1.y * rn, v1.x * rn);
            uint16_t p3 = f2e4m3x2(v1.w * rn, v1.z * rn);
            uint2 packed;
            packed.x = (uint32_t)p0 | ((uint32_t)p1 << 16);
            packed.y = (uint32_t)p2 | ((uint32_t)p3 << 16);
            ((uint2*)(g_zb + (size_t)row * DDIM))[lane] = packed;
            if (lane == 0) g_rowsum[row] = 0.0f;
        }
    }

    // ---------------- grid barrier 1 ----------------------------------------------
    if (tid == 0) {
        __threadfence();
        atomicAdd(&g_cnt1, 1u);
        while (*(volatile unsigned*)&g_cnt1 < NCTA) { }
        __threadfence();
    }
    __syncthreads();

    // ---------------- phase 2: symmetric FP8 GEMM (128x64 tiles) -------------------
    uint32_t d32 = smem_u32(dyn);
    char* base = dyn + ((1024u - (d32 & 1023u)) & 1023u);
    const uint32_t uA  = smem_u32(base);
    const uint32_t uB0 = uA + A_BYTES;
    const uint32_t uB1 = uB0 + B_BYTES;
    float* red_row = (float*)(base + A_BYTES + 2 * B_BYTES);   // [2][128]
    float* red_col = red_row + 2 * BM;                         // [4][64]

    const int hl = lane >> 4;
    uint32_t PA[2], SA[2];
    #pragma unroll
    for (int mf = 0; mf < 2; mf++) {
        int r = wm * 32 + mf * 16 + (lane & 15);
        PA[mf] = uA + (uint32_t)r * 256u + (uint32_t)((hl ^ (r & 1)) << 4);
        SA[mf] = (uint32_t)((r & 6) << 4);
    }
    uint32_t PBo[2], SB[2];
    #pragma unroll
    for (int ng = 0; ng < 2; ng++) {
        int rn = wn * 32 + ng * 16 + (lane & 15);
        PBo[ng] = (uint32_t)rn * 256u + (uint32_t)((hl ^ (rn & 1)) << 4);
        SB[ng] = (uint32_t)((rn & 6) << 4);
    }

    // balanced chunk over 4160 tiles: 16 CTAs get 15, rest 14 (296*14+16 = 4160)
    const int count = 14 + (cta < 16 ? 1 : 0);
    int rem = cta * 14 + (cta < 16 ? cta : 16);
    int p = 0;
    for (;;) {
        int L = 2 * (NTILE - rowof(p));
        if (rem < L) break;
        rem -= L;
        p++;
    }
    int off = rem;

    int ti = rowof(p);
    load_A(uA, ti * BM, tid);
    load_B(uB0, (2 * ti + off) * BN, tid);
    CP_COMMIT();
    int cur_ti = ti;

    for (int k = 0; k < count; k++) {
        ti = rowof(p);
        const int cj = 2 * ti + off;
        if (ti != cur_ti) {
            load_A(uA, ti * BM, tid);
            CP_COMMIT();
            cur_ti = ti;
        }
        CP_WAIT0();
        __syncthreads();

        if (k + 1 < count) {
            int p2 = p, o2 = off + 1;
            if (o2 >= 2 * (NTILE - rowof(p2))) { o2 = 0; p2++; }
            load_B((k & 1) ? uB0 : uB1, (2 * rowof(p2) + o2) * BN, tid);
            CP_COMMIT();
        }

        const uint32_t uBc = (k & 1) ? uB1 : uB0;
        const int i0 = ti * BM, j0 = cj * BN;
        const bool colsum = (off >= 2);
        const bool pairt = (ti < 32) && (off >= 64) && (off <= 65);

        float acc[2][4][4];
        #pragma unroll
        for (int mf = 0; mf < 2; mf++)
            #pragma unroll
            for (int nf = 0; nf < 4; nf++)
                #pragma unroll
                for (int c = 0; c < 4; c++) acc[mf][nf][c] = 0.0f;

        // ---- k-loop (8 steps of K=32), register double-buffered fragments ----
        uint32_t af[2][2][4], bfr[2][4][2];
        {
            #pragma unroll
            for (int mf = 0; mf < 2; mf++)
                ldsm_x4(PA[mf] + (0u ^ SA[mf]), af[0][mf]);
            #pragma unroll
            for (int ng = 0; ng < 2; ng++) {
                uint32_t q[4];
                ldsm_x4(uBc + PBo[ng] + (0u ^ SB[ng]), q);
                bfr[0][ng * 2 + 0][0] = q[0]; bfr[0][ng * 2 + 0][1] = q[2];
                bfr[0][ng * 2 + 1][0] = q[1]; bfr[0][ng * 2 + 1][1] = q[3];
            }
        }
        #pragma unroll
        for (int ks = 0; ks < 8; ks++) {
            const int cur = ks & 1, nxt = cur ^ 1;
            if (ks < 7) {
                const uint32_t kbit = (uint32_t)((ks + 1) << 5);
                #pragma unroll
                for (int mf = 0; mf < 2; mf++)
                    ldsm_x4(PA[mf] + (kbit ^ SA[mf]), af[nxt][mf]);
                #pragma unroll
                for (int ng = 0; ng < 2; ng++) {
                    uint32_t q[4];
                    ldsm_x4(uBc + PBo[ng] + (kbit ^ SB[ng]), q);
                    bfr[nxt][ng * 2 + 0][0] = q[0]; bfr[nxt][ng * 2 + 0][1] = q[2];
                    bfr[nxt][ng * 2 + 1][0] = q[1]; bfr[nxt][ng * 2 + 1][1] = q[3];
                }
            }
            #pragma unroll
            for (int mf = 0; mf < 2; mf++)
                #pragma unroll
                for (int nf = 0; nf < 4; nf++)
                    mma_fp8(acc[mf][nf], af[cur][mf], bfr[cur][nf]);
        }

        // ---- epilogue: pair capture, poly-exp, diagonal mask, row+col sums ----
        const int rloc = wm * 32 + (lane >> 2);
        const int cloc = wn * 32 + (lane & 3) * 2;
        float cs[8];
        #pragma unroll
        for (int x = 0; x < 8; x++) cs[x] = 0.0f;

        #pragma unroll
        for (int mf = 0; mf < 2; mf++) {
            const int rlo = i0 + rloc + mf * 16;
            const int rhi = rlo + 8;
            float slo = 0.0f, shi = 0.0f;
            #pragma unroll
            for (int nf = 0; nf < 4; nf++) {
                const int col = j0 + cloc + nf * 8;
                if (pairt) {
                    if ((rlo ^ NHALF) == col) {
                        float v = 2.0f * acc[mf][nf][0];
                        g_pair[rlo] = v; g_pair[col] = v;
                    }
                    if ((rlo ^ NHALF) == col + 1) {
                        float v = 2.0f * acc[mf][nf][1];
                        g_pair[rlo] = v; g_pair[col + 1] = v;
                    }
                    if ((rhi ^ NHALF) == col) {
                        float v = 2.0f * acc[mf][nf][2];
                        g_pair[rhi] = v; g_pair[col] = v;
                    }
                    if ((rhi ^ NHALF) == col + 1) {
                        float v = 2.0f * acc[mf][nf][3];
                        g_pair[rhi] = v; g_pair[col + 1] = v;
                    }
                }
                float e0 = fexp2a(acc[mf][nf][0]);
                float e1 = fexp2a(acc[mf][nf][1]);
                float e2 = fexp2a(acc[mf][nf][2]);
                float e3 = fexp2a(acc[mf][nf][3]);
                e0 = (rlo == col)     ? 0.0f : e0;
                e1 = (rlo == col + 1) ? 0.0f : e1;
                e2 = (rhi == col)     ? 0.0f : e2;
                e3 = (rhi == col + 1) ? 0.0f : e3;
                slo += e0 + e1;
                shi += e2 + e3;
                cs[nf * 2]     += e0 + e2;
                cs[nf * 2 + 1] += e1 + e3;
            }
            slo += __shfl_xor_sync(0xFFFFFFFFu, slo, 1);
            slo += __shfl_xor_sync(0xFFFFFFFFu, slo, 2);
            shi += __shfl_xor_sync(0xFFFFFFFFu, shi, 1);
            shi += __shfl_xor_sync(0xFFFFFFFFu, shi, 2);
            if ((lane & 3) == 0) {
                const int lrow = wm * 32 + mf * 16 + (lane >> 2);
                red_row[wn * BM + lrow] = slo;
                red_row[wn * BM + lrow + 8] = shi;
            }
        }
        if (colsum) {
            #pragma unroll
            for (int x = 0; x < 8; x++) {
                cs[x] += __shfl_xor_sync(0xFFFFFFFFu, cs[x], 4);
                cs[x] += __shfl_xor_sync(0xFFFFFFFFu, cs[x], 8);
                cs[x] += __shfl_xor_sync(0xFFFFFFFFu, cs[x], 16);
            }
            if (lane < 4) {
                #pragma unroll
                for (int nf = 0; nf < 4; nf++) {
                    const int c = wn * 32 + nf * 8 + lane * 2;
                    red_col[wm * BN + c]     = cs[nf * 2];
                    red_col[wm * BN + c + 1] = cs[nf * 2 + 1];
                }
            }
        }
        __syncthreads();
        if (tid < BM) {
            float s = red_row[tid] + red_row[BM + tid];
            atomicAdd(&g_rowsum[i0 + tid], s);
        } else if (tid < BM + BN && colsum) {
            const int c = tid - BM;
            float s = red_col[c] + red_col[BN + c]
                    + red_col[2 * BN + c] + red_col[3 * BN + c];
            atomicAdd(&g_rowsum[j0 + c], s);
        }

        off++;
        if (off >= 2 * (NTILE - ti)) { off = 0; p++; }
    }

    // ---------------- grid barrier 2 + CTA0 finish ---------------------------------
    if (tid == 0) {
        __threadfence();
        atomicAdd(&g_cnt2, 1u);
    }
    if (cta == 0) {
        if (tid == 0) {
            while (*(volatile unsigned*)&g_cnt2 < NCTA) { }
            __threadfence();
        }
        __syncthreads();
        __shared__ float sh[NTHREADS];
        float s = 0.0f;
        #pragma unroll
        for (int u = 0; u < NROWS / NTHREADS; u++) {
            const int r = tid + u * NTHREADS;
            s += logf(g_rowsum[r]) - g_pair[r];
        }
        sh[tid] = s;
        __syncthreads();
        for (int o2 = NTHREADS / 2; o2; o2 >>= 1) {
            if (tid < o2) sh[tid] += sh[tid + o2];
            __syncthreads();
        }
        if (tid == 0) {
            out[0] = sh[0] * (1.0f / (float)NROWS);
            g_cnt1 = 0;
            g_cnt2 = 0;
        }
    }
}

// ---------------------------------------------------------------- launch
extern "C" void kernel_launch(void* const* d_in, const int* in_sizes, int n_in,
                              void* d_out, int out_size) {
    const float* z1 = (const float*)d_in[0];
    const float* z2 = (const float*)d_in[1];
    float* out = (float*)d_out;

    static int smem_set = 0;
    if (!smem_set) {
        cudaFuncSetAttribute(k_fused, cudaFuncAttributeMaxDynamicSharedMemorySize,
                             DYN_BYTES);
        smem_set = 1;
    }

    k_fused<<<NCTA, NTHREADS, DYN_BYTES>>>(z1, z2, out);
}